// round 1
// baseline (speedup 1.0000x reference)
#include <cuda_runtime.h>

// Problem constants
#define B_  32
#define H_  4
#define L_  2048
#define D_  64
#define N_  32
#define P_  64
#define WN  63          // win_num
#define II  64          // N * win

#define WX_ELEMS 33030144   // B*H*II*WN*D  (also = B*II*WN*256 = NBHW*64*64)
#define M_QK     516096     // B*H*II*WN
#define M_V      129024     // B*II*WN
#define NBHW     8064       // B*H*WN
#define OUT_ELEMS 16777216  // B*L*H*D

// Scratch (static device globals — allocation-free per harness rules)
__device__ float g_wx[WX_ELEMS];   // [b][h][i][w][d]
__device__ float g_q [WX_ELEMS];
__device__ float g_k [WX_ELEMS];
__device__ float g_v [WX_ELEMS];   // [b][i][w][h*64+d]
__device__ float g_adj[WX_ELEMS];  // [b][h][w][i][j]
__device__ float g_o [WX_ELEMS];   // [b][h][w][i][d]

// ---------------------------------------------------------------------------
// 1. Gather wx: per (b,h), flat index F over (i,wn,dd) equals flat over
//    (n,d,w,e) with F = n*8064 + d*126 + 2w + e ; value = x[b,h,n*64+w+e,d]
// ---------------------------------------------------------------------------
__global__ __launch_bounds__(256) void k_build_wx(const float* __restrict__ x) {
    int idx = blockIdx.x * 256 + threadIdx.x;          // exact grid
    int bh  = idx / 258048;                            // II*WN*D_
    int F   = idx - bh * 258048;
    int n   = F / 8064;
    int r   = F - n * 8064;
    int d   = r / 126;
    int r2  = r - d * 126;
    int w   = r2 >> 1;
    int e   = r2 & 1;
    g_wx[idx] = x[(bh * L_ + n * P_ + w + e) * D_ + d];
}

// ---------------------------------------------------------------------------
// 2. Generic (M x 64) @ (64 x 64) + bias, rows contiguous. Used for q and kk.
// ---------------------------------------------------------------------------
__global__ __launch_bounds__(256) void k_gemm64(const float* __restrict__ A,
                                                const float* __restrict__ W,
                                                const float* __restrict__ bias,
                                                float* __restrict__ Dst) {
    __shared__ float As[64][65];
    __shared__ float Ws[64][64];
    int tid  = threadIdx.x;
    int base = blockIdx.x * 4096;
#pragma unroll
    for (int it = 0; it < 16; ++it) {
        int i2 = tid + it * 256;
        int rr = i2 >> 6, cc = i2 & 63;
        As[rr][cc] = A[base + i2];
        Ws[rr][cc] = W[i2];
    }
    __syncthreads();
    int ty = tid >> 4, tx = tid & 15;
    int r0 = ty * 4, c0 = tx * 4;
    float acc[4][4] = {};
#pragma unroll 4
    for (int k = 0; k < 64; ++k) {
        float a[4], wv[4];
#pragma unroll
        for (int i = 0; i < 4; ++i) a[i]  = As[r0 + i][k];
#pragma unroll
        for (int j = 0; j < 4; ++j) wv[j] = Ws[k][c0 + j];
#pragma unroll
        for (int i = 0; i < 4; ++i)
#pragma unroll
            for (int j = 0; j < 4; ++j) acc[i][j] += a[i] * wv[j];
    }
    float bb[4];
#pragma unroll
    for (int j = 0; j < 4; ++j) bb[j] = bias[c0 + j];
#pragma unroll
    for (int i = 0; i < 4; ++i)
#pragma unroll
        for (int j = 0; j < 4; ++j)
            Dst[base + (r0 + i) * 64 + c0 + j] = acc[i][j] + bb[j];
}

// ---------------------------------------------------------------------------
// 3. v = v_in @ Wv + bv.  v_in[b,i,w,h*64+d] = g_wx[b,h,i,w,d].
//    M=129024, K=256 (chunks of 64 == one h), Ncols=256 (4 col blocks).
// ---------------------------------------------------------------------------
__global__ __launch_bounds__(256) void k_v(const float* __restrict__ Wv,
                                           const float* __restrict__ bv) {
    __shared__ float As[64][65];
    __shared__ float Bs[64][64];
    int tid = threadIdx.x;
    int m0  = blockIdx.x * 64;
    int nc  = blockIdx.y;              // 0..3
    int ty = tid >> 4, tx = tid & 15;
    int r0 = ty * 4, c0 = tx * 4;
    float acc[4][4] = {};
    for (int kc = 0; kc < 4; ++kc) {   // kc == h
#pragma unroll
        for (int it = 0; it < 16; ++it) {
            int i2 = tid + it * 256;
            int rr = i2 >> 6, cc = i2 & 63;
            int m  = m0 + rr;
            int b  = m / 4032;         // II*WN
            int rem = m - b * 4032;
            int i  = rem / WN;
            int w  = rem - i * WN;
            As[rr][cc] = g_wx[(((b * H_ + kc) * II + i) * WN + w) * D_ + cc];
            Bs[rr][cc] = Wv[(kc * 64 + rr) * 256 + nc * 64 + cc];
        }
        __syncthreads();
#pragma unroll 4
        for (int k = 0; k < 64; ++k) {
            float a[4], wv[4];
#pragma unroll
            for (int i = 0; i < 4; ++i) a[i]  = As[r0 + i][k];
#pragma unroll
            for (int j = 0; j < 4; ++j) wv[j] = Bs[k][c0 + j];
#pragma unroll
            for (int i = 0; i < 4; ++i)
#pragma unroll
                for (int j = 0; j < 4; ++j) acc[i][j] += a[i] * wv[j];
        }
        __syncthreads();
    }
    float bb[4];
#pragma unroll
    for (int j = 0; j < 4; ++j) bb[j] = bv[nc * 64 + c0 + j];
#pragma unroll
    for (int i = 0; i < 4; ++i)
#pragma unroll
        for (int j = 0; j < 4; ++j)
            g_v[(m0 + r0 + i) * 256 + nc * 64 + c0 + j] = acc[i][j] + bb[j];
}

// ---------------------------------------------------------------------------
// 4. Per (b,h,w): A = Q_w K_w^T ; keep top-32 |A| per row (exact top_k tie
//    semantics); tanh; L1 row-normalize; store adj.
// ---------------------------------------------------------------------------
__global__ __launch_bounds__(256) void k_adj() {
    __shared__ float Qs[64][65];
    __shared__ float Ks[64][65];
    int tid = threadIdx.x;
    int bid = blockIdx.x;
    int w   = bid % WN;
    int bh  = bid / WN;
#pragma unroll
    for (int it = 0; it < 16; ++it) {
        int i2 = tid + it * 256;
        int rr = i2 >> 6, cc = i2 & 63;
        int src = ((bh * II + rr) * WN + w) * D_ + cc;
        Qs[rr][cc] = g_q[src];
        Ks[rr][cc] = g_k[src];
    }
    __syncthreads();
    int ty = tid >> 4, tx = tid & 15;
    int r0 = ty * 4, c0 = tx * 4;
    float acc[4][4] = {};
#pragma unroll 4
    for (int d = 0; d < 64; ++d) {
        float a[4], kv[4];
#pragma unroll
        for (int i = 0; i < 4; ++i) a[i]  = Qs[r0 + i][d];
#pragma unroll
        for (int j = 0; j < 4; ++j) kv[j] = Ks[c0 + j][d];
#pragma unroll
        for (int i = 0; i < 4; ++i)
#pragma unroll
            for (int j = 0; j < 4; ++j) acc[i][j] += a[i] * kv[j];
    }
    __syncthreads();              // everyone done reading Qs/Ks
#pragma unroll
    for (int i = 0; i < 4; ++i)
#pragma unroll
        for (int j = 0; j < 4; ++j) Qs[r0 + i][c0 + j] = acc[i][j];
    __syncthreads();

    // ranking: one warp handles one row at a time (8 rows per warp)
    int warp = tid >> 5, lane = tid & 31;
    int adjbase = bid * 4096;
    for (int r8 = 0; r8 < 8; ++r8) {
        int row = warp * 8 + r8;
        float a1 = Qs[row][lane];
        float a2 = Qs[row][lane + 32];
        float ab1 = fabsf(a1), ab2 = fabsf(a2);
        int c1 = 0, c2 = 0;
#pragma unroll 8
        for (int j = 0; j < 64; ++j) {
            float vj = fabsf(Qs[row][j]);
            c1 += (vj < ab1) || (vj == ab1 && j < lane);
            c2 += (vj < ab2) || (vj == ab2 && j < lane + 32);
        }
        float t1 = (c1 >= 32) ? tanhf(a1) : 0.f;
        float t2 = (c2 >= 32) ? tanhf(a2) : 0.f;
        float s = fabsf(t1) + fabsf(t2);
#pragma unroll
        for (int off = 16; off; off >>= 1) s += __shfl_xor_sync(0xffffffffu, s, off);
        float inv = 1.f / fmaxf(s, 1e-12f);
        g_adj[adjbase + row * 64 + lane]      = t1 * inv;
        g_adj[adjbase + row * 64 + lane + 32] = t2 * inv;
    }
}

// ---------------------------------------------------------------------------
// 5. loss = mean_{b,h,i,j} var_w(adj)   (ddof=0, two-pass for stability)
// ---------------------------------------------------------------------------
__global__ void k_loss_zero(float* __restrict__ out) { out[OUT_ELEMS] = 0.f; }

__global__ __launch_bounds__(256) void k_loss(float* __restrict__ out) {
    int idx = blockIdx.x * 256 + threadIdx.x;  // over B*H*64*64 = 524288
    int bh  = idx >> 12;
    int ij  = idx & 4095;
    const float* p = g_adj + bh * (WN * 4096) + ij;
    float s1 = 0.f;
#pragma unroll 7
    for (int w = 0; w < WN; ++w) s1 += p[w * 4096];
    float m = s1 * (1.f / 63.f);
    float s2 = 0.f;
#pragma unroll 7
    for (int w = 0; w < WN; ++w) { float dv = p[w * 4096] - m; s2 += dv * dv; }
    float var = s2 * (1.f / 63.f);
    __shared__ float red[256];
    red[threadIdx.x] = var;
    __syncthreads();
    for (int off = 128; off; off >>= 1) {
        if (threadIdx.x < off) red[threadIdx.x] += red[threadIdx.x + off];
        __syncthreads();
    }
    if (threadIdx.x == 0) atomicAdd(out + OUT_ELEMS, red[0] * (1.f / 524288.f));
}

// ---------------------------------------------------------------------------
// 6. Per (b,h,w): O = A_w @ V_w,  V_w[j][d] = g_v[b, j, w, h*64+d]
// ---------------------------------------------------------------------------
__global__ __launch_bounds__(256) void k_out() {
    __shared__ float As[64][65];
    __shared__ float Vs[64][65];
    int tid = threadIdx.x;
    int bid = blockIdx.x;
    int w   = bid % WN;
    int bh  = bid / WN;
    int b   = bh >> 2;
    int h   = bh & 3;
#pragma unroll
    for (int it = 0; it < 16; ++it) {
        int i2 = tid + it * 256;
        int rr = i2 >> 6, cc = i2 & 63;
        As[rr][cc] = g_adj[bid * 4096 + i2];
        Vs[rr][cc] = g_v[((b * II + rr) * WN + w) * 256 + h * 64 + cc];
    }
    __syncthreads();
    int ty = tid >> 4, tx = tid & 15;
    int r0 = ty * 4, c0 = tx * 4;
    float acc[4][4] = {};
#pragma unroll 4
    for (int j = 0; j < 64; ++j) {
        float a[4], vv[4];
#pragma unroll
        for (int i = 0; i < 4; ++i)  a[i]  = As[r0 + i][j];
#pragma unroll
        for (int jj = 0; jj < 4; ++jj) vv[jj] = Vs[j][c0 + jj];
#pragma unroll
        for (int i = 0; i < 4; ++i)
#pragma unroll
            for (int jj = 0; jj < 4; ++jj) acc[i][jj] += a[i] * vv[jj];
    }
#pragma unroll
    for (int i = 0; i < 4; ++i)
#pragma unroll
        for (int jj = 0; jj < 4; ++jj)
            g_o[bid * 4096 + (r0 + i) * 64 + c0 + jj] = acc[i][jj];
}

// ---------------------------------------------------------------------------
// 7. Final assembly: closed form of pad + pair-mean epilogue.
//    out[b, n*64+p, h*64+d]:
//      p==0  -> O[w=0 ][2n  ][d]
//      p==63 -> O[w=62][2n+1][d]
//      else  -> 0.5*(O[w=p][2n][d] + O[w=p-1][2n+1][d])
// ---------------------------------------------------------------------------
__global__ __launch_bounds__(256) void k_assemble(float* __restrict__ out) {
    int idx = blockIdx.x * 256 + threadIdx.x;  // exact OUT_ELEMS
    int d = idx & 63;
    int h = (idx >> 6) & 3;
    int p = (idx >> 8) & 63;
    int n = (idx >> 14) & 31;
    int b = idx >> 19;
    int bh = b * 4 + h;
    float val;
    if (p == 0) {
        val = g_o[((bh * WN + 0) * 64 + 2 * n) * 64 + d];
    } else if (p == 63) {
        val = g_o[((bh * WN + 62) * 64 + 2 * n + 1) * 64 + d];
    } else {
        float o0 = g_o[((bh * WN + p) * 64 + 2 * n) * 64 + d];
        float o1 = g_o[((bh * WN + p - 1) * 64 + 2 * n + 1) * 64 + d];
        val = 0.5f * (o0 + o1);
    }
    out[idx] = val;
}

// ---------------------------------------------------------------------------
extern "C" void kernel_launch(void* const* d_in, const int* in_sizes, int n_in,
                              void* d_out, int out_size) {
    const float* x  = (const float*)d_in[0];
    const float* W1 = (const float*)d_in[1];
    const float* b1 = (const float*)d_in[2];
    const float* W2 = (const float*)d_in[3];
    const float* b2 = (const float*)d_in[4];
    const float* Wv = (const float*)d_in[5];
    const float* bv = (const float*)d_in[6];
    float* out = (float*)d_out;

    float* wx = nullptr; float* q = nullptr; float* kk = nullptr;
    cudaGetSymbolAddress((void**)&wx, g_wx);
    cudaGetSymbolAddress((void**)&q,  g_q);
    cudaGetSymbolAddress((void**)&kk, g_k);

    k_build_wx<<<WX_ELEMS / 256, 256>>>(x);
    k_gemm64<<<M_QK / 64, 256>>>(wx, W1, b1, q);
    k_gemm64<<<M_QK / 64, 256>>>(wx, W2, b2, kk);
    k_v<<<dim3(M_V / 64, 4), 256>>>(Wv, bv);
    k_adj<<<NBHW, 256>>>();
    if (out_size > OUT_ELEMS) {
        k_loss_zero<<<1, 1>>>(out);
        k_loss<<<524288 / 256, 256>>>(out);
    }
    k_out<<<NBHW, 256>>>();
    k_assemble<<<OUT_ELEMS / 256, 256>>>(out);
}

// round 3
// speedup vs baseline: 1.1010x; 1.1010x over previous
#include <cuda_runtime.h>

// Problem constants
#define B_  32
#define H_  4
#define L_  2048
#define D_  64
#define N_  32
#define P_  64
#define WN  63          // win_num
#define II  64          // N * win

#define WX_ELEMS 33030144   // B*H*II*WN*D  (also = B*II*WN*256 = NBHW*64*64)
#define M_V      129024     // B*II*WN
#define NBHW     8064       // B*H*WN
#define OUT_ELEMS 16777216  // B*L*H*D

// Scratch (static device globals — allocation-free per harness rules)
__device__ float g_wx[WX_ELEMS];   // [b][h][i][w][d]
__device__ float g_v [WX_ELEMS];   // [b][i][w][h*64+d]
__device__ float g_adj[WX_ELEMS];  // [b][h][w][i][j]
__device__ float g_o [WX_ELEMS];   // [b][h][w][i][d]

// ---------------------------------------------------------------------------
// 1. Gather wx: per (b,h), flat index F over (i,wn,dd) equals flat over
//    (n,d,w,e) with F = n*8064 + d*126 + 2w + e ; value = x[b,h,n*64+w+e,d]
// ---------------------------------------------------------------------------
__global__ __launch_bounds__(256) void k_build_wx(const float* __restrict__ x) {
    int idx = blockIdx.x * 256 + threadIdx.x;          // exact grid
    int bh  = idx / 258048;                            // II*WN*D_
    int F   = idx - bh * 258048;
    int n   = F / 8064;
    int r   = F - n * 8064;
    int d   = r / 126;
    int r2  = r - d * 126;
    int w   = r2 >> 1;
    int e   = r2 & 1;
    g_wx[idx] = x[(bh * L_ + n * P_ + w + e) * D_ + d];
}

// ---------------------------------------------------------------------------
// 2. Fused per (b,h,w): Q = X@W1+b1, K = X@W2+b2 (shared X operand),
//    A = Q K^T, exact top-32-|.| keep mask, tanh, L1 row-normalize -> g_adj.
//    Static smem exactly 48KB: Xs (X, later A), U1 (W1, later Q),
//    U2 (W2, later K stored with +row column rotation for conflict-free K^T).
// ---------------------------------------------------------------------------
__global__ __launch_bounds__(256) void k_qk_adj(const float* __restrict__ W1,
                                                const float* __restrict__ b1,
                                                const float* __restrict__ W2,
                                                const float* __restrict__ b2) {
    __shared__ float Xs[64][64];
    __shared__ float U1[64][64];
    __shared__ float U2[64][64];
    int tid = threadIdx.x;
    int bid = blockIdx.x;
    int w   = bid % WN;
    int bh  = bid / WN;
#pragma unroll
    for (int it = 0; it < 16; ++it) {
        int i2 = tid + it * 256;
        int rr = i2 >> 6, cc = i2 & 63;
        Xs[rr][cc] = g_wx[((bh * II + rr) * WN + w) * D_ + cc];
        U1[rr][cc] = W1[i2];
        U2[rr][cc] = W2[i2];
    }
    __syncthreads();
    int ty = tid >> 4, tx = tid & 15;
    int r0 = ty * 4, c0 = tx * 4;

    // ---- Q and K together (shared A-operand loads) ----
    float q[4][4] = {}, kr[4][4] = {};
#pragma unroll 4
    for (int k = 0; k < 64; ++k) {
        float a[4], wq[4], wk[4];
#pragma unroll
        for (int i = 0; i < 4; ++i) a[i]  = Xs[r0 + i][k];
#pragma unroll
        for (int j = 0; j < 4; ++j) { wq[j] = U1[k][c0 + j]; wk[j] = U2[k][c0 + j]; }
#pragma unroll
        for (int i = 0; i < 4; ++i)
#pragma unroll
            for (int j = 0; j < 4; ++j) {
                q[i][j]  += a[i] * wq[j];
                kr[i][j] += a[i] * wk[j];
            }
    }
    __syncthreads();               // all W1/W2 reads done before overwrite
#pragma unroll
    for (int i = 0; i < 4; ++i)
#pragma unroll
        for (int j = 0; j < 4; ++j) {
            int rr = r0 + i, cc = c0 + j;
            U1[rr][cc] = q[i][j] + b1[cc];                 // Q
            U2[rr][(cc + rr) & 63] = kr[i][j] + b2[cc];    // K, rotated cols
        }
    __syncthreads();

    // ---- A = Q K^T ----
    float acc[4][4] = {};
#pragma unroll 4
    for (int d = 0; d < 64; ++d) {
        float qa[4], kb[4];
#pragma unroll
        for (int i = 0; i < 4; ++i) qa[i] = U1[r0 + i][d];
#pragma unroll
        for (int j = 0; j < 4; ++j) {
            int rr = c0 + j;
            kb[j] = U2[rr][(d + rr) & 63];
        }
#pragma unroll
        for (int i = 0; i < 4; ++i)
#pragma unroll
            for (int j = 0; j < 4; ++j) acc[i][j] += qa[i] * kb[j];
    }
    __syncthreads();               // Xs reads (none pending) + safe overwrite
#pragma unroll
    for (int i = 0; i < 4; ++i)
#pragma unroll
        for (int j = 0; j < 4; ++j) Xs[r0 + i][c0 + j] = acc[i][j];
    __syncthreads();

    // ---- ranking: exact top_k tie semantics; tanh; L1 normalize ----
    int warp = tid >> 5, lane = tid & 31;
    int adjbase = bid * 4096;
    for (int r8 = 0; r8 < 8; ++r8) {
        int row = warp * 8 + r8;
        float a1 = Xs[row][lane];
        float a2 = Xs[row][lane + 32];
        float ab1 = fabsf(a1), ab2 = fabsf(a2);
        int c1 = 0, c2 = 0;
#pragma unroll 8
        for (int j = 0; j < 64; ++j) {
            float vj = fabsf(Xs[row][j]);
            c1 += (vj < ab1) || (vj == ab1 && j < lane);
            c2 += (vj < ab2) || (vj == ab2 && j < lane + 32);
        }
        float t1 = (c1 >= 32) ? tanhf(a1) : 0.f;
        float t2 = (c2 >= 32) ? tanhf(a2) : 0.f;
        float s = fabsf(t1) + fabsf(t2);
#pragma unroll
        for (int off = 16; off; off >>= 1) s += __shfl_xor_sync(0xffffffffu, s, off);
        float inv = 1.f / fmaxf(s, 1e-12f);
        g_adj[adjbase + row * 64 + lane]      = t1 * inv;
        g_adj[adjbase + row * 64 + lane + 32] = t2 * inv;
    }
}

// ---------------------------------------------------------------------------
// 3. v = v_in @ Wv + bv, single pass over g_wx.
//    Block: 64 rows x 256 cols, K=256 in chunks of 32 with full-width B panel.
// ---------------------------------------------------------------------------
__global__ __launch_bounds__(256) void k_v2(const float* __restrict__ Wv,
                                            const float* __restrict__ bv) {
    __shared__ float As[64][33];
    __shared__ __align__(16) float Bs[32][256];
    int tid  = threadIdx.x;
    int m0   = blockIdx.x * 64;
    int b    = blockIdx.x / 63;            // 4032 rows per b, 63 blocks
    int rem0 = (blockIdx.x - b * 63) * 64;
    int ty = tid >> 4, tx = tid & 15;
    int r0 = ty * 4;
    float acc[4][16] = {};
    for (int ch = 0; ch < 8; ++ch) {       // global k = ch*32 + kk; h = ch>>1
#pragma unroll
        for (int it = 0; it < 8; ++it) {   // As: 64x32
            int i2 = tid + it * 256;
            int rr = i2 >> 5, kkc = i2 & 31;
            int rem = rem0 + rr;
            int i  = rem / WN;
            int ww = rem - i * WN;
            As[rr][kkc] = g_wx[(((b * H_ + (ch >> 1)) * II + i) * WN + ww) * D_ +
                               (ch & 1) * 32 + kkc];
        }
#pragma unroll
        for (int it = 0; it < 8; ++it) {   // Bs: 32x256 = 2048 float4
            int i4 = tid + it * 256;
            ((float4*)Bs)[i4] = ((const float4*)(Wv + ch * 32 * 256))[i4];
        }
        __syncthreads();
#pragma unroll 2
        for (int kk = 0; kk < 32; ++kk) {
            float a[4];
#pragma unroll
            for (int i = 0; i < 4; ++i) a[i] = As[r0 + i][kk];
#pragma unroll
            for (int nc = 0; nc < 4; ++nc) {
                float4 w4 = *(const float4*)&Bs[kk][nc * 64 + tx * 4];
#pragma unroll
                for (int i = 0; i < 4; ++i) {
                    acc[i][nc * 4 + 0] += a[i] * w4.x;
                    acc[i][nc * 4 + 1] += a[i] * w4.y;
                    acc[i][nc * 4 + 2] += a[i] * w4.z;
                    acc[i][nc * 4 + 3] += a[i] * w4.w;
                }
            }
        }
        __syncthreads();
    }
#pragma unroll
    for (int nc = 0; nc < 4; ++nc) {
        float4 bb = *(const float4*)&bv[nc * 64 + tx * 4];
#pragma unroll
        for (int i = 0; i < 4; ++i) {
            float4 o;
            o.x = acc[i][nc * 4 + 0] + bb.x;
            o.y = acc[i][nc * 4 + 1] + bb.y;
            o.z = acc[i][nc * 4 + 2] + bb.z;
            o.w = acc[i][nc * 4 + 3] + bb.w;
            *(float4*)&g_v[(m0 + r0 + i) * 256 + nc * 64 + tx * 4] = o;
        }
    }
}

// ---------------------------------------------------------------------------
// 4. loss = mean_{b,h,i,j} var_w(adj)   (ddof=0, two-pass)
// ---------------------------------------------------------------------------
__global__ void k_loss_zero(float* __restrict__ out) { out[OUT_ELEMS] = 0.f; }

__global__ __launch_bounds__(256) void k_loss(float* __restrict__ out) {
    int idx = blockIdx.x * 256 + threadIdx.x;  // over B*H*64*64 = 524288
    int bh  = idx >> 12;
    int ij  = idx & 4095;
    const float* p = g_adj + bh * (WN * 4096) + ij;
    float s1 = 0.f;
#pragma unroll 7
    for (int w = 0; w < WN; ++w) s1 += p[w * 4096];
    float m = s1 * (1.f / 63.f);
    float s2 = 0.f;
#pragma unroll 7
    for (int w = 0; w < WN; ++w) { float dv = p[w * 4096] - m; s2 += dv * dv; }
    float var = s2 * (1.f / 63.f);
    __shared__ float red[256];
    red[threadIdx.x] = var;
    __syncthreads();
    for (int off = 128; off; off >>= 1) {
        if (threadIdx.x < off) red[threadIdx.x] += red[threadIdx.x + off];
        __syncthreads();
    }
    if (threadIdx.x == 0) atomicAdd(out + OUT_ELEMS, red[0] * (1.f / 524288.f));
}

// ---------------------------------------------------------------------------
// 5. Per (b,h,w): O = A_w @ V_w,  V_w[j][d] = g_v[b, j, w, h*64+d]
// ---------------------------------------------------------------------------
__global__ __launch_bounds__(256) void k_out() {
    __shared__ float As[64][65];
    __shared__ float Vs[64][65];
    int tid = threadIdx.x;
    int bid = blockIdx.x;
    int w   = bid % WN;
    int bh  = bid / WN;
    int b   = bh >> 2;
    int h   = bh & 3;
#pragma unroll
    for (int it = 0; it < 16; ++it) {
        int i2 = tid + it * 256;
        int rr = i2 >> 6, cc = i2 & 63;
        As[rr][cc] = g_adj[bid * 4096 + i2];
        Vs[rr][cc] = g_v[((b * II + rr) * WN + w) * 256 + h * 64 + cc];
    }
    __syncthreads();
    int ty = tid >> 4, tx = tid & 15;
    int r0 = ty * 4, c0 = tx * 4;
    float acc[4][4] = {};
#pragma unroll 4
    for (int j = 0; j < 64; ++j) {
        float a[4], vv[4];
#pragma unroll
        for (int i = 0; i < 4; ++i)  a[i]  = As[r0 + i][j];
#pragma unroll
        for (int jj = 0; jj < 4; ++jj) vv[jj] = Vs[j][c0 + jj];
#pragma unroll
        for (int i = 0; i < 4; ++i)
#pragma unroll
            for (int jj = 0; jj < 4; ++jj) acc[i][jj] += a[i] * vv[jj];
    }
#pragma unroll
    for (int i = 0; i < 4; ++i)
#pragma unroll
        for (int jj = 0; jj < 4; ++jj)
            g_o[bid * 4096 + (r0 + i) * 64 + c0 + jj] = acc[i][jj];
}

// ---------------------------------------------------------------------------
// 6. Final assembly: closed form of pad + pair-mean epilogue.
//    out[b, n*64+p, h*64+d]:
//      p==0  -> O[w=0 ][2n  ][d]
//      p==63 -> O[w=62][2n+1][d]
//      else  -> 0.5*(O[w=p][2n][d] + O[w=p-1][2n+1][d])
// ---------------------------------------------------------------------------
__global__ __launch_bounds__(256) void k_assemble(float* __restrict__ out) {
    int idx = blockIdx.x * 256 + threadIdx.x;  // exact OUT_ELEMS
    int d = idx & 63;
    int h = (idx >> 6) & 3;
    int p = (idx >> 8) & 63;
    int n = (idx >> 14) & 31;
    int b = idx >> 19;
    int bh = b * 4 + h;
    float val;
    if (p == 0) {
        val = g_o[((bh * WN + 0) * 64 + 2 * n) * 64 + d];
    } else if (p == 63) {
        val = g_o[((bh * WN + 62) * 64 + 2 * n + 1) * 64 + d];
    } else {
        float o0 = g_o[((bh * WN + p) * 64 + 2 * n) * 64 + d];
        float o1 = g_o[((bh * WN + p - 1) * 64 + 2 * n + 1) * 64 + d];
        val = 0.5f * (o0 + o1);
    }
    out[idx] = val;
}

// ---------------------------------------------------------------------------
extern "C" void kernel_launch(void* const* d_in, const int* in_sizes, int n_in,
                              void* d_out, int out_size) {
    const float* x  = (const float*)d_in[0];
    const float* W1 = (const float*)d_in[1];
    const float* b1 = (const float*)d_in[2];
    const float* W2 = (const float*)d_in[3];
    const float* b2 = (const float*)d_in[4];
    const float* Wv = (const float*)d_in[5];
    const float* bv = (const float*)d_in[6];
    float* out = (float*)d_out;

    k_build_wx<<<WX_ELEMS / 256, 256>>>(x);
    k_qk_adj<<<NBHW, 256>>>(W1, b1, W2, b2);
    k_v2<<<M_V / 64, 256>>>(Wv, bv);
    if (out_size > OUT_ELEMS) {
        k_loss_zero<<<1, 1>>>(out);
        k_loss<<<524288 / 256, 256>>>(out);
    }
    k_out<<<NBHW, 256>>>();
    k_assemble<<<OUT_ELEMS / 256, 256>>>(out);
}

// round 6
// speedup vs baseline: 1.5843x; 1.4390x over previous
#include <cuda_runtime.h>
#include <cstdint>

// Problem constants
#define B_  32
#define H_  4
#define L_  2048
#define D_  64
#define N_  32
#define P_  64
#define WN  63          // win_num
#define II  64          // N * win

#define WX_ELEMS 33030144   // B*H*II*WN*D
#define M_V      129024     // B*II*WN
#define NBHW     8064       // B*H*WN
#define OUT_ELEMS 16777216  // B*L*H*D

// Scratch (static device globals — allocation-free per harness rules)
__device__ float g_wx[WX_ELEMS];   // [b][h][i][w][d]
__device__ float g_v [WX_ELEMS];   // [b][i][w][h*64+d]
__device__ float g_adj[WX_ELEMS];  // [b][h][w][i][j]
__device__ float g_o [WX_ELEMS];   // [b][h][w][i][d]

// ---------------------------------------------------------------------------
// tf32 helpers
// ---------------------------------------------------------------------------
__device__ __forceinline__ uint32_t f2tf32(float x) {
    uint32_t r;
    asm("cvt.rna.tf32.f32 %0, %1;" : "=r"(r) : "f"(x));
    return r;
}
__device__ __forceinline__ void split_tf32(float x, uint32_t& hi, uint32_t& lo) {
    asm("cvt.rna.tf32.f32 %0, %1;" : "=r"(hi) : "f"(x));
    float l = x - __uint_as_float(hi);
    asm("cvt.rna.tf32.f32 %0, %1;" : "=r"(lo) : "f"(l));
}
__device__ __forceinline__ void mma8(float* d, const uint32_t* a, const uint32_t* b) {
    asm volatile(
        "mma.sync.aligned.m16n8k8.row.col.f32.tf32.tf32.f32 "
        "{%0,%1,%2,%3}, {%4,%5,%6,%7}, {%8,%9}, {%0,%1,%2,%3};"
        : "+f"(d[0]), "+f"(d[1]), "+f"(d[2]), "+f"(d[3])
        : "r"(a[0]), "r"(a[1]), "r"(a[2]), "r"(a[3]), "r"(b[0]), "r"(b[1]));
}
// 3xTF32: d += a*b with near-fp32 accuracy (lo*hi, hi*lo, hi*hi)
__device__ __forceinline__ void mma3(float* d, const uint32_t* ah, const uint32_t* al,
                                     const uint32_t* bh, const uint32_t* bl) {
    mma8(d, al, bh);
    mma8(d, ah, bl);
    mma8(d, ah, bh);
}

// ---------------------------------------------------------------------------
// 1. Gather wx, coalesced: one block per (bh, n); stage 64x64 x-tile in smem.
//    g_wx flat-per-(bh): F = n*8064 + d*126 + 2w + e ; val = x[bh, n*64+w+e, d]
// ---------------------------------------------------------------------------
__global__ __launch_bounds__(256) void k_build_wx(const float* __restrict__ x) {
    __shared__ float xs[64][65];
    int bid = blockIdx.x;          // bh*32 + n, 4096 blocks
    int bh  = bid >> 5;
    int n   = bid & 31;
    int tid = threadIdx.x;
#pragma unroll
    for (int it = 0; it < 16; ++it) {
        int i2 = tid + it * 256;
        int rr = i2 >> 6, cc = i2 & 63;
        xs[rr][cc] = x[(bh * L_ + n * P_ + rr) * D_ + cc];
    }
    __syncthreads();
    float* dst = g_wx + bh * 258048 + n * 8064;
    for (int j = tid; j < 8064; j += 256) {
        int d  = j / 126;
        int r2 = j - d * 126;
        int row = (r2 >> 1) + (r2 & 1);     // w + e
        dst[j] = xs[row][d];
    }
}

// ---------------------------------------------------------------------------
// 2. Fused per (b,h,w): Q=XW1+b1, K=XW2+b2, A=QK^T (all 3xTF32 tensor core),
//    exact top-32 |.| mask, tanh, L1 row-normalize -> g_adj.
//    smem exactly 48KB: Xs (X, later A), U1 (W1 -> Q), U2 (W2 -> K).
// ---------------------------------------------------------------------------
__global__ __launch_bounds__(256) void k_qk_adj(const float* __restrict__ W1,
                                                const float* __restrict__ b1,
                                                const float* __restrict__ W2,
                                                const float* __restrict__ b2) {
    __shared__ float Xs[64][64];
    __shared__ float U1[64][64];
    __shared__ float U2[64][64];
    int tid = threadIdx.x;
    int bid = blockIdx.x;
    int w   = bid % WN;
    int bh  = bid / WN;
#pragma unroll
    for (int it = 0; it < 16; ++it) {
        int i2 = tid + it * 256;
        int rr = i2 >> 6, cc = i2 & 63;
        Xs[rr][cc] = g_wx[((bh * II + rr) * WN + w) * D_ + cc];
        U1[rr][cc] = W1[i2];
        U2[rr][cc] = W2[i2];
    }
    __syncthreads();

    int warp = tid >> 5, lane = tid & 31;
    int g = lane >> 2, tq = lane & 3;

    // ---- Phase 1: warps 0-3 -> Q strips, warps 4-7 -> K strips (16x64 each)
    {
        int ms = (warp & 3) * 16;
        bool isK = warp >= 4;
        float (*Wop)[64] = isK ? U2 : U1;
        float acc[8][4];
#pragma unroll
        for (int nt = 0; nt < 8; ++nt)
#pragma unroll
            for (int c = 0; c < 4; ++c) acc[nt][c] = 0.f;
#pragma unroll
        for (int ks = 0; ks < 8; ++ks) {
            int k0 = ks * 8;
            uint32_t ah[4], al[4];
            split_tf32(Xs[ms + g][k0 + tq],         ah[0], al[0]);
            split_tf32(Xs[ms + g + 8][k0 + tq],     ah[1], al[1]);
            split_tf32(Xs[ms + g][k0 + tq + 4],     ah[2], al[2]);
            split_tf32(Xs[ms + g + 8][k0 + tq + 4], ah[3], al[3]);
#pragma unroll
            for (int nt = 0; nt < 8; ++nt) {
                uint32_t bhv[2], blv[2];
                split_tf32(Wop[k0 + tq][nt * 8 + g],     bhv[0], blv[0]);
                split_tf32(Wop[k0 + tq + 4][nt * 8 + g], bhv[1], blv[1]);
                mma3(acc[nt], ah, al, bhv, blv);
            }
        }
        __syncthreads();   // all W1/W2 reads done before overwrite
        const float* bias = isK ? b2 : b1;
        float (*Udst)[64] = isK ? U2 : U1;
#pragma unroll
        for (int nt = 0; nt < 8; ++nt) {
            int n0 = nt * 8 + 2 * tq;
            float bb0 = bias[n0], bb1 = bias[n0 + 1];
            Udst[ms + g][n0]         = acc[nt][0] + bb0;
            Udst[ms + g][n0 + 1]     = acc[nt][1] + bb1;
            Udst[ms + g + 8][n0]     = acc[nt][2] + bb0;
            Udst[ms + g + 8][n0 + 1] = acc[nt][3] + bb1;
        }
        __syncthreads();
    }

    // ---- Phase 2: A = Q K^T. Warp tile: 16 x 32.
    {
        int ms = (warp & 3) * 16;
        int nh = (warp >> 2) * 32;
        float acc[4][4];
#pragma unroll
        for (int nt = 0; nt < 4; ++nt)
#pragma unroll
            for (int c = 0; c < 4; ++c) acc[nt][c] = 0.f;
#pragma unroll
        for (int ks = 0; ks < 8; ++ks) {
            int k0 = ks * 8;
            uint32_t ah[4], al[4];
            split_tf32(U1[ms + g][k0 + tq],         ah[0], al[0]);
            split_tf32(U1[ms + g + 8][k0 + tq],     ah[1], al[1]);
            split_tf32(U1[ms + g][k0 + tq + 4],     ah[2], al[2]);
            split_tf32(U1[ms + g + 8][k0 + tq + 4], ah[3], al[3]);
#pragma unroll
            for (int nt = 0; nt < 4; ++nt) {
                int j0 = nh + nt * 8 + g;
                uint32_t bhv[2], blv[2];
                split_tf32(U2[j0][k0 + tq],     bhv[0], blv[0]);
                split_tf32(U2[j0][k0 + tq + 4], bhv[1], blv[1]);
                mma3(acc[nt], ah, al, bhv, blv);
            }
        }
#pragma unroll
        for (int nt = 0; nt < 4; ++nt) {
            int n0 = nh + nt * 8 + 2 * tq;
            Xs[ms + g][n0]         = acc[nt][0];
            Xs[ms + g][n0 + 1]     = acc[nt][1];
            Xs[ms + g + 8][n0]     = acc[nt][2];
            Xs[ms + g + 8][n0 + 1] = acc[nt][3];
        }
        __syncthreads();
    }

    // ---- ranking: exact top_k tie semantics; tanh; L1 normalize ----
    int adjbase = bid * 4096;
    for (int r8 = 0; r8 < 8; ++r8) {
        int row = warp * 8 + r8;
        float a1 = Xs[row][lane];
        float a2 = Xs[row][lane + 32];
        float ab1 = fabsf(a1), ab2 = fabsf(a2);
        int c1 = 0, c2 = 0;
#pragma unroll 8
        for (int j = 0; j < 64; ++j) {
            float vj = fabsf(Xs[row][j]);
            c1 += (vj < ab1) || (vj == ab1 && j < lane);
            c2 += (vj < ab2) || (vj == ab2 && j < lane + 32);
        }
        float t1 = (c1 >= 32) ? tanhf(a1) : 0.f;
        float t2 = (c2 >= 32) ? tanhf(a2) : 0.f;
        float s = fabsf(t1) + fabsf(t2);
#pragma unroll
        for (int off = 16; off; off >>= 1) s += __shfl_xor_sync(0xffffffffu, s, off);
        float inv = 1.f / fmaxf(s, 1e-12f);
        g_adj[adjbase + row * 64 + lane]      = t1 * inv;
        g_adj[adjbase + row * 64 + lane + 32] = t2 * inv;
    }
}

// ---------------------------------------------------------------------------
// 3. v = v_in @ Wv + bv  (1xTF32 tensor core). 64 rows x 256 cols per block.
//    K=256 in 8 chunks of 32; Wv chunk pre-converted to tf32 in smem.
// ---------------------------------------------------------------------------
__global__ __launch_bounds__(256) void k_v2(const float* __restrict__ Wv,
                                            const float* __restrict__ bv) {
    __shared__ float As[64][33];
    __shared__ __align__(16) uint32_t Bs[32][264];
    int tid  = threadIdx.x;
    int m0   = blockIdx.x * 64;
    int b    = blockIdx.x / 63;
    int rem0 = (blockIdx.x - b * 63) * 64;
    int warp = tid >> 5, lane = tid & 31;
    int g = lane >> 2, tq = lane & 3;
    int ms = (warp & 3) * 16;
    int nh = (warp >> 2) * 128;
    float acc[16][4];
#pragma unroll
    for (int nt = 0; nt < 16; ++nt)
#pragma unroll
        for (int c = 0; c < 4; ++c) acc[nt][c] = 0.f;

    for (int ch = 0; ch < 8; ++ch) {       // global k = ch*32 + kk; h = ch>>1
#pragma unroll
        for (int it = 0; it < 8; ++it) {   // As: 64x32
            int i2 = tid + it * 256;
            int rr = i2 >> 5, kkc = i2 & 31;
            int rem = rem0 + rr;
            int i  = rem / WN;
            int ww = rem - i * WN;
            As[rr][kkc] = g_wx[(((b * H_ + (ch >> 1)) * II + i) * WN + ww) * D_ +
                               (ch & 1) * 32 + kkc];
        }
#pragma unroll
        for (int it = 0; it < 8; ++it) {   // Bs: 32x256, cvt to tf32
            int i4 = tid + it * 256;
            int r  = i4 >> 6;
            int c  = (i4 & 63) * 4;
            float4 v4 = *(const float4*)&Wv[(ch * 32 + r) * 256 + c];
            uint4 t;
            t.x = f2tf32(v4.x); t.y = f2tf32(v4.y);
            t.z = f2tf32(v4.z); t.w = f2tf32(v4.w);
            *(uint4*)&Bs[r][c] = t;
        }
        __syncthreads();
#pragma unroll
        for (int ks = 0; ks < 4; ++ks) {
            int k0 = ks * 8;
            uint32_t a[4];
            a[0] = f2tf32(As[ms + g][k0 + tq]);
            a[1] = f2tf32(As[ms + g + 8][k0 + tq]);
            a[2] = f2tf32(As[ms + g][k0 + tq + 4]);
            a[3] = f2tf32(As[ms + g + 8][k0 + tq + 4]);
#pragma unroll
            for (int nt = 0; nt < 16; ++nt) {
                uint32_t bb[2];
                int n0 = nh + nt * 8 + g;
                bb[0] = Bs[k0 + tq][n0];
                bb[1] = Bs[k0 + tq + 4][n0];
                mma8(acc[nt], a, bb);
            }
        }
        __syncthreads();
    }
#pragma unroll
    for (int nt = 0; nt < 16; ++nt) {
        int n0 = nh + nt * 8 + 2 * tq;
        float bb0 = bv[n0], bb1 = bv[n0 + 1];
        g_v[(m0 + ms + g) * 256 + n0]         = acc[nt][0] + bb0;
        g_v[(m0 + ms + g) * 256 + n0 + 1]     = acc[nt][1] + bb1;
        g_v[(m0 + ms + g + 8) * 256 + n0]     = acc[nt][2] + bb0;
        g_v[(m0 + ms + g + 8) * 256 + n0 + 1] = acc[nt][3] + bb1;
    }
}

// ---------------------------------------------------------------------------
// 4. loss = mean_{b,h,i,j} var_w(adj)   (ddof=0, two-pass)
// ---------------------------------------------------------------------------
__global__ void k_loss_zero(float* __restrict__ out) { out[OUT_ELEMS] = 0.f; }

__global__ __launch_bounds__(256) void k_loss(float* __restrict__ out) {
    int idx = blockIdx.x * 256 + threadIdx.x;  // over B*H*64*64 = 524288
    int bh  = idx >> 12;
    int ij  = idx & 4095;
    const float* p = g_adj + bh * (WN * 4096) + ij;
    float s1 = 0.f;
#pragma unroll 7
    for (int w = 0; w < WN; ++w) s1 += p[w * 4096];
    float m = s1 * (1.f / 63.f);
    float s2 = 0.f;
#pragma unroll 7
    for (int w = 0; w < WN; ++w) { float dv = p[w * 4096] - m; s2 += dv * dv; }
    float var = s2 * (1.f / 63.f);
    __shared__ float red[256];
    red[threadIdx.x] = var;
    __syncthreads();
    for (int off = 128; off; off >>= 1) {
        if (threadIdx.x < off) red[threadIdx.x] += red[threadIdx.x + off];
        __syncthreads();
    }
    if (threadIdx.x == 0) atomicAdd(out + OUT_ELEMS, red[0] * (1.f / 524288.f));
}

// ---------------------------------------------------------------------------
// 5. Per (b,h,w): O = A_w @ V_w (1xTF32 tensor core).
//    V_w[j][d] = g_v[b, j, w, h*64+d]
// ---------------------------------------------------------------------------
__global__ __launch_bounds__(256) void k_out() {
    __shared__ float As[64][65];
    __shared__ float Vs[64][72];
    int tid = threadIdx.x;
    int bid = blockIdx.x;
    int w   = bid % WN;
    int bh  = bid / WN;
    int b   = bh >> 2;
    int h   = bh & 3;
#pragma unroll
    for (int it = 0; it < 16; ++it) {
        int i2 = tid + it * 256;
        int rr = i2 >> 6, cc = i2 & 63;
        As[rr][cc] = g_adj[bid * 4096 + i2];
        Vs[rr][cc] = g_v[((b * II + rr) * WN + w) * 256 + h * 64 + cc];
    }
    __syncthreads();
    int warp = tid >> 5, lane = tid & 31;
    int g = lane >> 2, tq = lane & 3;
    int ms = (warp & 3) * 16;
    int nh = (warp >> 2) * 32;
    float acc[4][4];
#pragma unroll
    for (int nt = 0; nt < 4; ++nt)
#pragma unroll
        for (int c = 0; c < 4; ++c) acc[nt][c] = 0.f;
#pragma unroll
    for (int ks = 0; ks < 8; ++ks) {
        int k0 = ks * 8;
        uint32_t a[4];
        a[0] = f2tf32(As[ms + g][k0 + tq]);
        a[1] = f2tf32(As[ms + g + 8][k0 + tq]);
        a[2] = f2tf32(As[ms + g][k0 + tq + 4]);
        a[3] = f2tf32(As[ms + g + 8][k0 + tq + 4]);
#pragma unroll
        for (int nt = 0; nt < 4; ++nt) {
            int n0 = nh + nt * 8 + g;
            uint32_t bb[2];
            bb[0] = f2tf32(Vs[k0 + tq][n0]);
            bb[1] = f2tf32(Vs[k0 + tq + 4][n0]);
            mma8(acc[nt], a, bb);
        }
    }
#pragma unroll
    for (int nt = 0; nt < 4; ++nt) {
        int n0 = nh + nt * 8 + 2 * tq;
        g_o[bid * 4096 + (ms + g) * 64 + n0]         = acc[nt][0];
        g_o[bid * 4096 + (ms + g) * 64 + n0 + 1]     = acc[nt][1];
        g_o[bid * 4096 + (ms + g + 8) * 64 + n0]     = acc[nt][2];
        g_o[bid * 4096 + (ms + g + 8) * 64 + n0 + 1] = acc[nt][3];
    }
}

// ---------------------------------------------------------------------------
// 6. Final assembly: closed form of pad + pair-mean epilogue.
// ---------------------------------------------------------------------------
__global__ __launch_bounds__(256) void k_assemble(float* __restrict__ out) {
    int idx = blockIdx.x * 256 + threadIdx.x;  // exact OUT_ELEMS
    int d = idx & 63;
    int h = (idx >> 6) & 3;
    int p = (idx >> 8) & 63;
    int n = (idx >> 14) & 31;
    int b = idx >> 19;
    int bh = b * 4 + h;
    float val;
    if (p == 0) {
        val = g_o[((bh * WN + 0) * 64 + 2 * n) * 64 + d];
    } else if (p == 63) {
        val = g_o[((bh * WN + 62) * 64 + 2 * n + 1) * 64 + d];
    } else {
        float o0 = g_o[((bh * WN + p) * 64 + 2 * n) * 64 + d];
        float o1 = g_o[((bh * WN + p - 1) * 64 + 2 * n + 1) * 64 + d];
        val = 0.5f * (o0 + o1);
    }
    out[idx] = val;
}

// ---------------------------------------------------------------------------
extern "C" void kernel_launch(void* const* d_in, const int* in_sizes, int n_in,
                              void* d_out, int out_size) {
    const float* x  = (const float*)d_in[0];
    const float* W1 = (const float*)d_in[1];
    const float* b1 = (const float*)d_in[2];
    const float* W2 = (const float*)d_in[3];
    const float* b2 = (const float*)d_in[4];
    const float* Wv = (const float*)d_in[5];
    const float* bv = (const float*)d_in[6];
    float* out = (float*)d_out;

    k_build_wx<<<4096, 256>>>(x);
    k_qk_adj<<<NBHW, 256>>>(W1, b1, W2, b2);
    k_v2<<<M_V / 64, 256>>>(Wv, bv);
    if (out_size > OUT_ELEMS) {
        k_loss_zero<<<1, 1>>>(out);
        k_loss<<<524288 / 256, 256>>>(out);
    }
    k_out<<<NBHW, 256>>>();
    k_assemble<<<OUT_ELEMS / 256, 256>>>(out);
}